// round 10
// baseline (speedup 1.0000x reference)
#include <cuda_runtime.h>

// CrimeModelLSTM: 2-layer LSTM (H=8), B=4096, T=512, FC head [4,8].
// R10 = R3 core (best: 113us) with three trims:
//  (1) dup-MOV elimination: operand pairs (h,h) built by TWO shuffles (width-8
//      and width-32 encodings, same source lane) writing lo/hi halves directly
//      — removes 16 guaranteed MOVs/step from the FMA/ALU issue path.
//  (2) (1+tanh) cell algebra: 2ig=fma(ti,tg,tg), 2fc=fma(tf,c,c); h kept as 2h
//      with 0.5 folded into consumer weights (wh1, wi2, wh2, Wfc).
//  (3) final-iteration peel (drops the prefetch-clamp SEL).
// fma.rn.f32x2 gate-pair packing, tanh.approx activations, cross-layer
// software pipelining (body computes L2(t) and L1(t+1)) kept from R3.

typedef unsigned long long u64;

__device__ __forceinline__ u64 pk2(float lo, float hi) {
    u64 r; asm("mov.b64 %0, {%1,%2};" : "=l"(r) : "f"(lo), "f"(hi)); return r;
}
__device__ __forceinline__ void upk(u64 v, float& lo, float& hi) {
    asm("mov.b64 {%0,%1}, %2;" : "=f"(lo), "=f"(hi) : "l"(v));
}
__device__ __forceinline__ u64 fma2(u64 a, u64 b, u64 c) {
    u64 d; asm("fma.rn.f32x2 %0, %1, %2, %3;" : "=l"(d) : "l"(a), "l"(b), "l"(c)); return d;
}
__device__ __forceinline__ float tanhap(float x) {
    float r; asm("tanh.approx.f32 %0, %1;" : "=f"(r) : "f"(x)); return r;
}

__global__ void __launch_bounds__(32)
lstm2_kernel(const float* __restrict__ x,
             const float* __restrict__ Wih1, const float* __restrict__ Whh1,
             const float* __restrict__ bih1, const float* __restrict__ bhh1,
             const float* __restrict__ Wih2, const float* __restrict__ Whh2,
             const float* __restrict__ bih2, const float* __restrict__ bhh2,
             const float* __restrict__ Wfc,  const float* __restrict__ bfc,
             float* __restrict__ out)
{
    constexpr int T = 512;
    constexpr int H = 8;

    const int tid  = blockIdx.x * 32 + threadIdx.x;
    const int e    = tid >> 3;             // batch element
    const int j    = tid & 7;              // hidden unit owned
    const int base = threadIdx.x & 24;     // first lane of this 8-lane group

    // absolute source lanes for the width-32 shuffles (loop-invariant)
    int laneB[H];
    #pragma unroll
    for (int k = 0; k < H; k++) laneB[k] = base + k;

    // gate scales (i,f,g,o): sigmoid rows fold 0.5; tanh row 1.0
    const float gsc[4] = {0.5f, 0.5f, 1.0f, 0.5f};

    // ---- weights packed as gate pairs: pair0=(i,f), pair1=(g,o) ----
    // h carried as 2h -> extra 0.5 on all h-consuming weights
    u64 wh1p[2][H], wi2p[2][H], wh2p[2][H];
    u64 wx1p[2], bb1p[2], bb2p[2];
    #pragma unroll
    for (int p = 0; p < 2; p++) {
        const int gA = 2 * p, gB = 2 * p + 1;
        const int rA = gA * 8 + j, rB = gB * 8 + j;
        const float sA = gsc[gA], sB = gsc[gB];
        wx1p[p] = pk2(Wih1[rA] * sA, Wih1[rB] * sB);
        bb1p[p] = pk2((bih1[rA] + bhh1[rA]) * sA, (bih1[rB] + bhh1[rB]) * sB);
        bb2p[p] = pk2((bih2[rA] + bhh2[rA]) * sA, (bih2[rB] + bhh2[rB]) * sB);
        #pragma unroll
        for (int k = 0; k < H; k++) {
            wh1p[p][k] = pk2(Whh1[rA * H + k] * sA * 0.5f,
                             Whh1[rB * H + k] * sB * 0.5f);
            wi2p[p][k] = pk2(Wih2[rA * H + k] * sA * 0.5f,
                             Wih2[rB * H + k] * sB * 0.5f);
            wh2p[p][k] = pk2(Whh2[rA * H + k] * sA * 0.5f,
                             Whh2[rB * H + k] * sB * 0.5f);
        }
    }

    // ---- state: h pairs hold (2h, 2h) ----
    u64 h1d[H], h2d[H];
    #pragma unroll
    for (int k = 0; k < H; k++) { h1d[k] = 0ull; h2d[k] = 0ull; }
    float c1 = 0.0f, c2 = 0.0f;

    const float4* __restrict__ xp = reinterpret_cast<const float4*>(x + (long)e * T);
    float4 xv = xp[0];

    // ---- prologue: L1 step 0 (h1 = 0: only x term) ----
    {
        u64 x2 = pk2(xv.x, xv.x);
        u64 P0 = fma2(wx1p[0], x2, bb1p[0]);
        u64 P1 = fma2(wx1p[1], x2, bb1p[1]);
        float a, b;
        upk(P0, a, b); const float ti = tanhap(a), tf = tanhap(b);
        upk(P1, a, b); const float tg = tanhap(a), to = tanhap(b);
        const float A  = fmaf(ti, tg, tg);          // 2*i*g
        const float Zf = fmaf(tf, c1, c1);          // 2*f*c (= 0 here)
        c1 = (A + Zf) * 0.5f;
        const float tc = tanhap(c1);
        const float h1o = fmaf(to, tc, tc);         // = 2*h1
        #pragma unroll
        for (int k = 0; k < H; k++) {
            const float lo = __shfl_sync(0xffffffffu, h1o, k, 8);
            const float hi = __shfl_sync(0xffffffffu, h1o, laneB[k]);
            h1d[k] = pk2(lo, hi);
        }
    }

    // step body: computes L2(t) and L1(t+1); both consume h1(t)
    #define STEP_BODY(XT)                                                     \
    {                                                                         \
        u64 x2 = pk2((XT), (XT));                                             \
        u64 P1_0 = fma2(wx1p[0], x2, bb1p[0]);                                \
        u64 P1_1 = fma2(wx1p[1], x2, bb1p[1]);                                \
        u64 P2_0 = bb2p[0];                                                   \
        u64 P2_1 = bb2p[1];                                                   \
        _Pragma("unroll")                                                     \
        for (int k = 0; k < H; k++) {                                         \
            const u64 h = h1d[k];                                             \
            P2_0 = fma2(wi2p[0][k], h, P2_0);                                 \
            P2_1 = fma2(wi2p[1][k], h, P2_1);                                 \
            P1_0 = fma2(wh1p[0][k], h, P1_0);                                 \
            P1_1 = fma2(wh1p[1][k], h, P1_1);                                 \
        }                                                                     \
        _Pragma("unroll")                                                     \
        for (int k = 0; k < H; k++) {                                         \
            const u64 h = h2d[k];                                             \
            P2_0 = fma2(wh2p[0][k], h, P2_0);                                 \
            P2_1 = fma2(wh2p[1][k], h, P2_1);                                 \
        }                                                                     \
        float a, b;                                                           \
        upk(P1_0, a, b); const float ti1 = tanhap(a), tf1 = tanhap(b);        \
        upk(P1_1, a, b); const float tg1 = tanhap(a), to1 = tanhap(b);        \
        upk(P2_0, a, b); const float ti2 = tanhap(a), tf2 = tanhap(b);        \
        upk(P2_1, a, b); const float tg2 = tanhap(a), to2 = tanhap(b);        \
        const float A1  = fmaf(ti1, tg1, tg1);                                \
        const float Z1  = fmaf(tf1, c1, c1);                                  \
        const float A2  = fmaf(ti2, tg2, tg2);                                \
        const float Z2  = fmaf(tf2, c2, c2);                                  \
        c1 = (A1 + Z1) * 0.5f;                                                \
        c2 = (A2 + Z2) * 0.5f;                                                \
        const float tc1 = tanhap(c1);                                         \
        const float tc2 = tanhap(c2);                                         \
        const float h1o = fmaf(to1, tc1, tc1);  /* 2*h1 */                    \
        const float h2o = fmaf(to2, tc2, tc2);  /* 2*h2 */                    \
        _Pragma("unroll")                                                     \
        for (int k = 0; k < H; k++) {                                         \
            const float lo1 = __shfl_sync(0xffffffffu, h1o, k, 8);            \
            const float hi1 = __shfl_sync(0xffffffffu, h1o, laneB[k]);        \
            const float lo2 = __shfl_sync(0xffffffffu, h2o, k, 8);            \
            const float hi2 = __shfl_sync(0xffffffffu, h2o, laneB[k]);        \
            h1d[k] = pk2(lo1, hi1);                                           \
            h2d[k] = pk2(lo2, hi2);                                           \
        }                                                                     \
    }

    // ---- main loop (peeled final block: no prefetch clamp SEL) ----
    for (int tt = 0; tt < T / 4 - 1; ++tt) {
        float4 xn = xp[tt + 1];
        STEP_BODY(xv.y);
        STEP_BODY(xv.z);
        STEP_BODY(xv.w);
        STEP_BODY(xn.x);
        xv = xn;
    }
    {   // final block: steps T-3..T-1 need x; the 4th body's L1 output is unused
        STEP_BODY(xv.y);
        STEP_BODY(xv.z);
        STEP_BODY(xv.w);
        STEP_BODY(xv.w);
    }
    #undef STEP_BODY

    // ---- FC head: h2d[k].lo = 2*h2(T-1)[k]; fold the 0.5 into Wfc ----
    if (j < 4) {
        float acc = bfc[j];
        #pragma unroll
        for (int k = 0; k < H; k++) {
            float lo, hi;
            upk(h2d[k], lo, hi); (void)hi;
            acc = fmaf(Wfc[j * H + k] * 0.5f, lo, acc);
        }
        out[e * 4 + j] = acc;
    }
}

extern "C" void kernel_launch(void* const* d_in, const int* in_sizes, int n_in,
                              void* d_out, int out_size)
{
    const float* x    = (const float*)d_in[0];
    const float* Wih1 = (const float*)d_in[1];
    const float* Whh1 = (const float*)d_in[2];
    const float* bih1 = (const float*)d_in[3];
    const float* bhh1 = (const float*)d_in[4];
    const float* Wih2 = (const float*)d_in[5];
    const float* Whh2 = (const float*)d_in[6];
    const float* bih2 = (const float*)d_in[7];
    const float* bhh2 = (const float*)d_in[8];
    const float* Wfc  = (const float*)d_in[9];
    const float* bfc  = (const float*)d_in[10];
    float* out = (float*)d_out;

    const int B = 4096;
    dim3 grid(B * 8 / 32), block(32);
    lstm2_kernel<<<grid, block>>>(x, Wih1, Whh1, bih1, bhh1,
                                  Wih2, Whh2, bih2, bhh2, Wfc, bfc, out);
}

// round 12
// speedup vs baseline: 1.0223x; 1.0223x over previous
#include <cuda_runtime.h>

// CrimeModelLSTM: 2-layer LSTM (H=8), B=4096, T=512, FC head [4,8].
// R12 = R11 resubmit (infra failure last round; kernel never evaluated).
// R11 = R3 core (best: 113us) with the 32-instr shuffle/dup communication
// block replaced by a 13-instr smem broadcast:
//   per step: 2x pk2 + 2x STS.64 (dup-pairs of h1o,h2o) + 1 __syncwarp +
//             8x LDS.128 (reload all 16 dup-pair operands).
// Double-buffered slots (compile-time, via the 4-step unroll) + the single
// syncwarp make cross-step reuse race-free. Rows padded to 80B -> the four
// group addresses land in disjoint bank ranges (no LDS conflicts).
// Kept from R3/R10: fma.rn.f32x2 gate-pair packing, tanh.approx activations,
// (1+tanh) cell algebra with h carried as 2h (0.5 folded into consumer
// weights), cross-layer software pipelining (body does L2(t) and L1(t+1)).

typedef unsigned long long u64;

__device__ __forceinline__ u64 pk2(float lo, float hi) {
    u64 r; asm("mov.b64 %0, {%1,%2};" : "=l"(r) : "f"(lo), "f"(hi)); return r;
}
__device__ __forceinline__ void upk(u64 v, float& lo, float& hi) {
    asm("mov.b64 {%0,%1}, %2;" : "=f"(lo), "=f"(hi) : "l"(v));
}
__device__ __forceinline__ u64 fma2(u64 a, u64 b, u64 c) {
    u64 d; asm("fma.rn.f32x2 %0, %1, %2, %3;" : "=l"(d) : "l"(a), "l"(b), "l"(c)); return d;
}
__device__ __forceinline__ float tanhap(float x) {
    float r; asm("tanh.approx.f32 %0, %1;" : "=f"(r) : "f"(x)); return r;
}

__global__ void __launch_bounds__(32)
lstm2_kernel(const float* __restrict__ x,
             const float* __restrict__ Wih1, const float* __restrict__ Whh1,
             const float* __restrict__ bih1, const float* __restrict__ bhh1,
             const float* __restrict__ Wih2, const float* __restrict__ Whh2,
             const float* __restrict__ bih2, const float* __restrict__ bhh2,
             const float* __restrict__ Wfc,  const float* __restrict__ bfc,
             float* __restrict__ out)
{
    constexpr int T = 512;
    constexpr int H = 8;

    const int tid = blockIdx.x * 32 + threadIdx.x;
    const int e   = tid >> 3;              // batch element
    const int j   = tid & 7;               // hidden unit owned
    const int grp = (threadIdx.x >> 3) & 3;

    // double-buffered dup-pair staging; [10] pads rows to 80B: 16B-aligned
    // rows AND disjoint bank ranges for the 4 group addresses.
    __shared__ alignas(16) u64 s1[2][4][10];
    __shared__ alignas(16) u64 s2[2][4][10];

    // gate scales (i,f,g,o): sigmoid rows fold 0.5; tanh row 1.0
    const float gsc[4] = {0.5f, 0.5f, 1.0f, 0.5f};

    // ---- weights packed as gate pairs: pair0=(i,f), pair1=(g,o) ----
    // h carried as 2h -> extra 0.5 on all h-consuming weights
    u64 wh1p[2][H], wi2p[2][H], wh2p[2][H];
    u64 wx1p[2], bb1p[2], bb2p[2];
    #pragma unroll
    for (int p = 0; p < 2; p++) {
        const int gA = 2 * p, gB = 2 * p + 1;
        const int rA = gA * 8 + j, rB = gB * 8 + j;
        const float sA = gsc[gA], sB = gsc[gB];
        wx1p[p] = pk2(Wih1[rA] * sA, Wih1[rB] * sB);
        bb1p[p] = pk2((bih1[rA] + bhh1[rA]) * sA, (bih1[rB] + bhh1[rB]) * sB);
        bb2p[p] = pk2((bih2[rA] + bhh2[rA]) * sA, (bih2[rB] + bhh2[rB]) * sB);
        #pragma unroll
        for (int k = 0; k < H; k++) {
            wh1p[p][k] = pk2(Whh1[rA * H + k] * sA * 0.5f,
                             Whh1[rB * H + k] * sB * 0.5f);
            wi2p[p][k] = pk2(Wih2[rA * H + k] * sA * 0.5f,
                             Wih2[rB * H + k] * sB * 0.5f);
            wh2p[p][k] = pk2(Whh2[rA * H + k] * sA * 0.5f,
                             Whh2[rB * H + k] * sB * 0.5f);
        }
    }

    // ---- state: dup-pair operands (2h, 2h) live in registers between steps
    u64 h1d[H], h2d[H];
    float c1 = 0.0f, c2 = 0.0f;

    const float4* __restrict__ xp = reinterpret_cast<const float4*>(x + (long)e * T);
    float4 xv = xp[0];

    // ---- prologue: L1 step 0 (h1 = 0: only x term); stage into slot 1 ----
    {
        u64 x2 = pk2(xv.x, xv.x);
        u64 P0 = fma2(wx1p[0], x2, bb1p[0]);
        u64 P1 = fma2(wx1p[1], x2, bb1p[1]);
        float a, b;
        upk(P0, a, b); const float ti = tanhap(a), tf = tanhap(b); (void)tf;
        upk(P1, a, b); const float tg = tanhap(a), to = tanhap(b);
        const float A = fmaf(ti, tg, tg);      // 2*i*g (c=0: no f-term)
        c1 = A * 0.5f;
        const float tc = tanhap(c1);
        const float h1o = fmaf(to, tc, tc);    // = 2*h1
        s1[1][grp][j] = pk2(h1o, h1o);
        s2[1][grp][j] = 0ull;                  // h2(-1) = 0
        __syncwarp();
        const ulonglong2* r1 = reinterpret_cast<const ulonglong2*>(&s1[1][grp][0]);
        const ulonglong2* r2 = reinterpret_cast<const ulonglong2*>(&s2[1][grp][0]);
        #pragma unroll
        for (int i = 0; i < 4; i++) {
            ulonglong2 a1 = r1[i], a2 = r2[i];
            h1d[2*i] = a1.x; h1d[2*i+1] = a1.y;
            h2d[2*i] = a2.x; h2d[2*i+1] = a2.y;
        }
    }

    // step body: computes L2(t) and L1(t+1); both consume h1(t).
    // SLOT is compile-time: writes slot SLOT, reloads from it.
    #define STEP_BODY(XT, SLOT)                                               \
    {                                                                         \
        u64 x2 = pk2((XT), (XT));                                             \
        u64 P1_0 = fma2(wx1p[0], x2, bb1p[0]);                                \
        u64 P1_1 = fma2(wx1p[1], x2, bb1p[1]);                                \
        u64 P2_0 = bb2p[0];                                                   \
        u64 P2_1 = bb2p[1];                                                   \
        _Pragma("unroll")                                                     \
        for (int k = 0; k < H; k++) {                                         \
            const u64 h = h1d[k];                                             \
            P2_0 = fma2(wi2p[0][k], h, P2_0);                                 \
            P2_1 = fma2(wi2p[1][k], h, P2_1);                                 \
            P1_0 = fma2(wh1p[0][k], h, P1_0);                                 \
            P1_1 = fma2(wh1p[1][k], h, P1_1);                                 \
        }                                                                     \
        _Pragma("unroll")                                                     \
        for (int k = 0; k < H; k++) {                                         \
            const u64 h = h2d[k];                                             \
            P2_0 = fma2(wh2p[0][k], h, P2_0);                                 \
            P2_1 = fma2(wh2p[1][k], h, P2_1);                                 \
        }                                                                     \
        float a, b;                                                           \
        upk(P1_0, a, b); const float ti1 = tanhap(a), tf1 = tanhap(b);        \
        upk(P1_1, a, b); const float tg1 = tanhap(a), to1 = tanhap(b);        \
        upk(P2_0, a, b); const float ti2 = tanhap(a), tf2 = tanhap(b);        \
        upk(P2_1, a, b); const float tg2 = tanhap(a), to2 = tanhap(b);        \
        const float A1 = fmaf(ti1, tg1, tg1);                                 \
        const float Z1 = fmaf(tf1, c1, c1);                                   \
        const float A2 = fmaf(ti2, tg2, tg2);                                 \
        const float Z2 = fmaf(tf2, c2, c2);                                   \
        c1 = (A1 + Z1) * 0.5f;                                                \
        c2 = (A2 + Z2) * 0.5f;                                                \
        const float tc1 = tanhap(c1);                                         \
        const float tc2 = tanhap(c2);                                         \
        const float h1o = fmaf(to1, tc1, tc1);  /* 2*h1 */                    \
        const float h2o = fmaf(to2, tc2, tc2);  /* 2*h2 */                    \
        s1[SLOT][grp][j] = pk2(h1o, h1o);                                     \
        s2[SLOT][grp][j] = pk2(h2o, h2o);                                     \
        __syncwarp();                                                         \
        const ulonglong2* r1 =                                                \
            reinterpret_cast<const ulonglong2*>(&s1[SLOT][grp][0]);           \
        const ulonglong2* r2 =                                                \
            reinterpret_cast<const ulonglong2*>(&s2[SLOT][grp][0]);           \
        _Pragma("unroll")                                                     \
        for (int i = 0; i < 4; i++) {                                         \
            ulonglong2 a1 = r1[i], a2 = r2[i];                                \
            h1d[2*i] = a1.x; h1d[2*i+1] = a1.y;                               \
            h2d[2*i] = a2.x; h2d[2*i+1] = a2.y;                               \
        }                                                                     \
    }

    // ---- main loop: 4 steps/iter, slots alternate 0,1,0,1 (prologue = 1) ----
    for (int tt = 0; tt < T / 4; ++tt) {
        const int nxt = (tt + 1 < T / 4) ? (tt + 1) : tt;
        float4 xn = xp[nxt];
        STEP_BODY(xv.y, 0);
        STEP_BODY(xv.z, 1);
        STEP_BODY(xv.w, 0);
        STEP_BODY(xn.x, 1);
        xv = xn;
    }
    #undef STEP_BODY
    // last body's L1 (step T) used clamped x and is unused; h2d = 2*h2(T-1).

    // ---- FC head: h2d[k].lo = 2*h2(T-1)[k]; fold the 0.5 into Wfc ----
    if (j < 4) {
        float acc = bfc[j];
        #pragma unroll
        for (int k = 0; k < H; k++) {
            float lo, hi;
            upk(h2d[k], lo, hi); (void)hi;
            acc = fmaf(Wfc[j * H + k] * 0.5f, lo, acc);
        }
        out[e * 4 + j] = acc;
    }
}

extern "C" void kernel_launch(void* const* d_in, const int* in_sizes, int n_in,
                              void* d_out, int out_size)
{
    const float* x    = (const float*)d_in[0];
    const float* Wih1 = (const float*)d_in[1];
    const float* Whh1 = (const float*)d_in[2];
    const float* bih1 = (const float*)d_in[3];
    const float* bhh1 = (const float*)d_in[4];
    const float* Wih2 = (const float*)d_in[5];
    const float* Whh2 = (const float*)d_in[6];
    const float* bih2 = (const float*)d_in[7];
    const float* bhh2 = (const float*)d_in[8];
    const float* Wfc  = (const float*)d_in[9];
    const float* bfc  = (const float*)d_in[10];
    float* out = (float*)d_out;

    const int B = 4096;
    dim3 grid(B * 8 / 32), block(32);
    lstm2_kernel<<<grid, block>>>(x, Wih1, Whh1, bih1, bhh1,
                                  Wih2, Whh2, bih2, bhh2, Wfc, bfc, out);
}

// round 13
// speedup vs baseline: 1.0932x; 1.0694x over previous
#include <cuda_runtime.h>

// CrimeModelLSTM: 2-layer LSTM (H=8), B=4096, T=512, FC head [4,8].
// R13 = R3 compute core with UNIFORM-OCCUPANCY launch geometry:
//   grid = 128 CTAs x 256 threads (8 warps/CTA, 32 elements/CTA).
//   128 CTAs < 148 SMs -> exactly 1 CTA/SM -> exactly 2 warps per SMSP on
//   every active SM. The old 1024x32 launch left ~25% of SMSPs with a single
//   warp (6.92 warps/SM); those unhidden-latency stragglers set the wall.
// Compute kept from R3 (+validated trims): fma.rn.f32x2 gate-pair packing,
// tanh.approx activations, (1+tanh) cell algebra with h carried as 2h (0.5
// folded into consumer weights), cross-layer software pipelining
// (body computes L2(t) and L1(t+1)), shfl+dup-mov h broadcast (best measured).

typedef unsigned long long u64;

__device__ __forceinline__ u64 pk2(float lo, float hi) {
    u64 r; asm("mov.b64 %0, {%1,%2};" : "=l"(r) : "f"(lo), "f"(hi)); return r;
}
__device__ __forceinline__ void upk(u64 v, float& lo, float& hi) {
    asm("mov.b64 {%0,%1}, %2;" : "=f"(lo), "=f"(hi) : "l"(v));
}
__device__ __forceinline__ u64 fma2(u64 a, u64 b, u64 c) {
    u64 d; asm("fma.rn.f32x2 %0, %1, %2, %3;" : "=l"(d) : "l"(a), "l"(b), "l"(c)); return d;
}
__device__ __forceinline__ float tanhap(float x) {
    float r; asm("tanh.approx.f32 %0, %1;" : "=f"(r) : "f"(x)); return r;
}

__global__ void __launch_bounds__(256, 1)
lstm2_kernel(const float* __restrict__ x,
             const float* __restrict__ Wih1, const float* __restrict__ Whh1,
             const float* __restrict__ bih1, const float* __restrict__ bhh1,
             const float* __restrict__ Wih2, const float* __restrict__ Whh2,
             const float* __restrict__ bih2, const float* __restrict__ bhh2,
             const float* __restrict__ Wfc,  const float* __restrict__ bfc,
             float* __restrict__ out)
{
    constexpr int T = 512;
    constexpr int H = 8;

    const int tid = blockIdx.x * 256 + threadIdx.x;
    const int e   = tid >> 3;       // batch element (8 threads each)
    const int j   = tid & 7;        // hidden unit owned by this thread

    // gate scales (i,f,g,o): sigmoid rows fold 0.5; tanh row 1.0
    const float gsc[4] = {0.5f, 0.5f, 1.0f, 0.5f};

    // ---- weights packed as gate pairs: pair0=(i,f), pair1=(g,o) ----
    // h carried as 2h -> extra 0.5 on all h-consuming weights
    u64 wh1p[2][H], wi2p[2][H], wh2p[2][H];
    u64 wx1p[2], bb1p[2], bb2p[2];
    #pragma unroll
    for (int p = 0; p < 2; p++) {
        const int gA = 2 * p, gB = 2 * p + 1;
        const int rA = gA * 8 + j, rB = gB * 8 + j;
        const float sA = gsc[gA], sB = gsc[gB];
        wx1p[p] = pk2(Wih1[rA] * sA, Wih1[rB] * sB);
        bb1p[p] = pk2((bih1[rA] + bhh1[rA]) * sA, (bih1[rB] + bhh1[rB]) * sB);
        bb2p[p] = pk2((bih2[rA] + bhh2[rA]) * sA, (bih2[rB] + bhh2[rB]) * sB);
        #pragma unroll
        for (int k = 0; k < H; k++) {
            wh1p[p][k] = pk2(Whh1[rA * H + k] * sA * 0.5f,
                             Whh1[rB * H + k] * sB * 0.5f);
            wi2p[p][k] = pk2(Wih2[rA * H + k] * sA * 0.5f,
                             Wih2[rB * H + k] * sB * 0.5f);
            wh2p[p][k] = pk2(Whh2[rA * H + k] * sA * 0.5f,
                             Whh2[rB * H + k] * sB * 0.5f);
        }
    }

    // ---- state: dup-pair operands (2h, 2h) ----
    u64 h1d[H], h2d[H];
    #pragma unroll
    for (int k = 0; k < H; k++) { h1d[k] = 0ull; h2d[k] = 0ull; }
    float c1 = 0.0f, c2 = 0.0f;

    const float4* __restrict__ xp = reinterpret_cast<const float4*>(x + (long)e * T);
    float4 xv = xp[0];

    // ---- prologue: L1 step 0 (h1 = 0: only x term) ----
    {
        u64 x2 = pk2(xv.x, xv.x);
        u64 P0 = fma2(wx1p[0], x2, bb1p[0]);
        u64 P1 = fma2(wx1p[1], x2, bb1p[1]);
        float a, b;
        upk(P0, a, b); const float ti = tanhap(a), tf = tanhap(b); (void)tf;
        upk(P1, a, b); const float tg = tanhap(a), to = tanhap(b);
        c1 = fmaf(ti, tg, tg) * 0.5f;          // (2ig)/2, c was 0
        const float tc = tanhap(c1);
        const float h1o = fmaf(to, tc, tc);    // = 2*h1
        #pragma unroll
        for (int k = 0; k < H; k++) {
            const float v = __shfl_sync(0xffffffffu, h1o, k, 8);
            h1d[k] = pk2(v, v);
        }
    }

    // ---- main loop: body computes L2(t) and L1(t+1); both consume h1(t) ----
    for (int tt = 0; tt < T / 4; ++tt) {
        const int nxt = (tt + 1 < T / 4) ? (tt + 1) : tt;
        float4 xn = xp[nxt];
        float xs[4] = {xv.y, xv.z, xv.w, xn.x};  // x for L1 step t+1

        #pragma unroll
        for (int q = 0; q < 4; q++) {
            u64 x2 = pk2(xs[q], xs[q]);
            u64 P1_0 = fma2(wx1p[0], x2, bb1p[0]);
            u64 P1_1 = fma2(wx1p[1], x2, bb1p[1]);
            u64 P2_0 = bb2p[0];
            u64 P2_1 = bb2p[1];
            #pragma unroll
            for (int k = 0; k < H; k++) {
                const u64 h = h1d[k];
                P2_0 = fma2(wi2p[0][k], h, P2_0);
                P2_1 = fma2(wi2p[1][k], h, P2_1);
                P1_0 = fma2(wh1p[0][k], h, P1_0);
                P1_1 = fma2(wh1p[1][k], h, P1_1);
            }
            #pragma unroll
            for (int k = 0; k < H; k++) {
                const u64 h = h2d[k];
                P2_0 = fma2(wh2p[0][k], h, P2_0);
                P2_1 = fma2(wh2p[1][k], h, P2_1);
            }

            float a, b;
            upk(P1_0, a, b); const float ti1 = tanhap(a), tf1 = tanhap(b);
            upk(P1_1, a, b); const float tg1 = tanhap(a), to1 = tanhap(b);
            upk(P2_0, a, b); const float ti2 = tanhap(a), tf2 = tanhap(b);
            upk(P2_1, a, b); const float tg2 = tanhap(a), to2 = tanhap(b);

            const float A1 = fmaf(ti1, tg1, tg1);   // 2*i*g
            const float Z1 = fmaf(tf1, c1, c1);     // 2*f*c
            const float A2 = fmaf(ti2, tg2, tg2);
            const float Z2 = fmaf(tf2, c2, c2);
            c1 = (A1 + Z1) * 0.5f;
            c2 = (A2 + Z2) * 0.5f;
            const float tc1 = tanhap(c1);
            const float tc2 = tanhap(c2);
            const float h1o = fmaf(to1, tc1, tc1);  // = 2*h1
            const float h2o = fmaf(to2, tc2, tc2);  // = 2*h2

            #pragma unroll
            for (int k = 0; k < H; k++) {
                const float v1 = __shfl_sync(0xffffffffu, h1o, k, 8);
                const float v2 = __shfl_sync(0xffffffffu, h2o, k, 8);
                h1d[k] = pk2(v1, v1);
                h2d[k] = pk2(v2, v2);
            }
        }
        xv = xn;
    }
    // loop produced h2 = 2*h2(T-1) in h2d; final (extra) L1 result unused.

    // ---- FC head: h2d[k].lo = 2*h2(T-1)[k]; fold the 0.5 into Wfc ----
    if (j < 4) {
        float acc = bfc[j];
        #pragma unroll
        for (int k = 0; k < H; k++) {
            float lo, hi;
            upk(h2d[k], lo, hi); (void)hi;
            acc = fmaf(Wfc[j * H + k] * 0.5f, lo, acc);
        }
        out[e * 4 + j] = acc;
    }
}

extern "C" void kernel_launch(void* const* d_in, const int* in_sizes, int n_in,
                              void* d_out, int out_size)
{
    const float* x    = (const float*)d_in[0];
    const float* Wih1 = (const float*)d_in[1];
    const float* Whh1 = (const float*)d_in[2];
    const float* bih1 = (const float*)d_in[3];
    const float* bhh1 = (const float*)d_in[4];
    const float* Wih2 = (const float*)d_in[5];
    const float* Whh2 = (const float*)d_in[6];
    const float* bih2 = (const float*)d_in[7];
    const float* bhh2 = (const float*)d_in[8];
    const float* Wfc  = (const float*)d_in[9];
    const float* bfc  = (const float*)d_in[10];
    float* out = (float*)d_out;

    const int B = 4096;
    // 8 threads/element, 256-thread CTAs -> 128 CTAs (< 148 SMs):
    // exactly 1 CTA/SM, exactly 2 warps per SMSP on every active SM.
    dim3 grid(B * 8 / 256), block(256);
    lstm2_kernel<<<grid, block>>>(x, Wih1, Whh1, bih1, bhh1,
                                  Wih2, Whh2, bih2, bhh2, Wfc, bfc, out);
}